// round 9
// baseline (speedup 1.0000x reference)
#include <cuda_runtime.h>
#include <cuda_bf16.h>
#include <math.h>
#include <stdint.h>

// Problem constants (fixed by setup_inputs): B=2048, K=128, D=256
#define BB 2048
#define KK 128
#define DD 256

#define BM 32       // b-rows per block
#define BN 32       // k-cols per block
#define PB 264      // row pitch in bf16 units (528 bytes; 16B-aligned, conflict-free ldmatrix)
#define NTHREADS 256

__device__ __forceinline__ uint32_t cvta_smem(const void* p) {
    return (uint32_t)__cvta_generic_to_shared(p);
}

__device__ __forceinline__ void ldmat_x4(uint32_t* r, uint32_t addr) {
    asm volatile("ldmatrix.sync.aligned.m8n8.x4.shared.b16 {%0,%1,%2,%3}, [%4];"
                 : "=r"(r[0]), "=r"(r[1]), "=r"(r[2]), "=r"(r[3]) : "r"(addr));
}

__device__ __forceinline__ void mma_bf16(float* d, const uint32_t* a, uint32_t b0, uint32_t b1) {
    asm volatile("mma.sync.aligned.m16n8k16.row.col.f32.bf16.bf16.f32 "
                 "{%0,%1,%2,%3}, {%4,%5,%6,%7}, {%8,%9}, {%0,%1,%2,%3};"
                 : "+f"(d[0]), "+f"(d[1]), "+f"(d[2]), "+f"(d[3])
                 : "r"(a[0]), "r"(a[1]), "r"(a[2]), "r"(a[3]), "r"(b0), "r"(b1));
}

__device__ __forceinline__ uint32_t bits2(__nv_bfloat162 v) {
    return *reinterpret_cast<uint32_t*>(&v);
}

// logits[b][k] = 2*an_k * asinh( 2*(S*xa + T*ya)*den / (den^2 - (S^2*x2 + 2*S*T*xy + T^2*y2)) )
// g = z_k . y_b, xy = s_k*g, ya = t_k*g, S = 1+2xy+y2, den = 1+2xy+x2*y2, T = 1-x2

__global__ void __launch_bounds__(NTHREADS, 2)
mlr_logits_kernel(const float* __restrict__ Y,   // output_before (B, D)
                  const float* __restrict__ Z,   // z_mlr (K, D)
                  const float* __restrict__ R,   // mlr_r (K, 1)
                  float* __restrict__ Out)       // (B, K)
{
    extern __shared__ char smem[];
    __nv_bfloat16* AHI = reinterpret_cast<__nv_bfloat16*>(smem);           // BM*PB
    __nv_bfloat16* ALO = AHI + BM * PB;                                     // BM*PB
    __nv_bfloat16* ZHI = ALO + BM * PB;                                     // BN*PB
    __nv_bfloat16* ZLO = ZHI + BN * PB;                                     // BN*PB
    float* part  = reinterpret_cast<float*>(ZLO + BN * PB);                 // 128 (y partials)
    float* zprt  = part + 128;                                              // 128 (z partials)
    float* s_s   = zprt + 128;                                              // BN
    float* s_t   = s_s + BN;
    float* s_x2  = s_t + BN;
    float* s_xa  = s_x2 + BN;
    float* s_an2 = s_xa + BN;
    float* s_y2  = s_an2 + BN;                                              // BM

    const int tid  = threadIdx.x;
    const int b0   = blockIdx.x * BM;
    const int k0   = blockIdx.y * BN;
    const int warp = tid >> 5;
    const int lane = tid & 31;

    // ---- load + bf16-split Y tile (BM x D) and Z tile (BN x D) ----
    #pragma unroll
    for (int idx = tid; idx < BM * (DD / 4); idx += NTHREADS) {
        int row = idx >> 6;
        int c4  = idx & 63;
        float4 v = reinterpret_cast<const float4*>(Y + (size_t)(b0 + row) * DD)[c4];
        __nv_bfloat162 h01 = __float22bfloat162_rn(make_float2(v.x, v.y));
        __nv_bfloat162 h23 = __float22bfloat162_rn(make_float2(v.z, v.w));
        float2 hf01 = __bfloat1622float2(h01);
        float2 hf23 = __bfloat1622float2(h23);
        __nv_bfloat162 l01 = __float22bfloat162_rn(make_float2(v.x - hf01.x, v.y - hf01.y));
        __nv_bfloat162 l23 = __float22bfloat162_rn(make_float2(v.z - hf23.x, v.w - hf23.y));
        *reinterpret_cast<uint2*>(&AHI[row * PB + c4 * 4]) = make_uint2(bits2(h01), bits2(h23));
        *reinterpret_cast<uint2*>(&ALO[row * PB + c4 * 4]) = make_uint2(bits2(l01), bits2(l23));
    }
    #pragma unroll
    for (int idx = tid; idx < BN * (DD / 4); idx += NTHREADS) {
        int row = idx >> 6;
        int c4  = idx & 63;
        float4 v = reinterpret_cast<const float4*>(Z + (size_t)(k0 + row) * DD)[c4];
        __nv_bfloat162 h01 = __float22bfloat162_rn(make_float2(v.x, v.y));
        __nv_bfloat162 h23 = __float22bfloat162_rn(make_float2(v.z, v.w));
        float2 hf01 = __bfloat1622float2(h01);
        float2 hf23 = __bfloat1622float2(h23);
        __nv_bfloat162 l01 = __float22bfloat162_rn(make_float2(v.x - hf01.x, v.y - hf01.y));
        __nv_bfloat162 l23 = __float22bfloat162_rn(make_float2(v.z - hf23.x, v.w - hf23.y));
        *reinterpret_cast<uint2*>(&ZHI[row * PB + c4 * 4]) = make_uint2(bits2(h01), bits2(h23));
        *reinterpret_cast<uint2*>(&ZLO[row * PB + c4 * 4]) = make_uint2(bits2(l01), bits2(l23));
    }
    __syncthreads();

    // ---- row norms, Y and Z concurrently: 4 threads per row ----
    {
        const int half = tid >> 7;          // 0: Y rows, 1: Z rows
        const int lid7 = tid & 127;
        const int row  = lid7 >> 2;         // 0..31
        const int q    = lid7 & 3;
        const __nv_bfloat16* hiB = half ? ZHI : AHI;
        const __nv_bfloat16* loB = half ? ZLO : ALO;
        const uint4* ph = reinterpret_cast<const uint4*>(&hiB[row * PB + q * 64]);
        const uint4* pl = reinterpret_cast<const uint4*>(&loB[row * PB + q * 64]);
        float acc = 0.f;
        #pragma unroll
        for (int j = 0; j < 8; j++) {
            uint4 h = ph[j], l = pl[j];
            const uint32_t hw[4] = {h.x, h.y, h.z, h.w};
            const uint32_t lw[4] = {l.x, l.y, l.z, l.w};
            #pragma unroll
            for (int m = 0; m < 4; m++) {
                float2 hf = __bfloat1622float2(*reinterpret_cast<const __nv_bfloat162*>(&hw[m]));
                float2 lf = __bfloat1622float2(*reinterpret_cast<const __nv_bfloat162*>(&lw[m]));
                float v0 = hf.x + lf.x, v1 = hf.y + lf.y;
                acc = fmaf(v0, v0, acc);
                acc = fmaf(v1, v1, acc);
            }
        }
        if (half) zprt[lid7] = acc; else part[lid7] = acc;
    }
    __syncthreads();

    if (tid < BM) {
        s_y2[tid] = (part[tid * 4 + 0] + part[tid * 4 + 1]) +
                    (part[tid * 4 + 2] + part[tid * 4 + 3]);
    } else if (tid < BM + BN) {
        int row = tid - BM;
        float zn2 = (zprt[row * 4 + 0] + zprt[row * 4 + 1]) +
                    (zprt[row * 4 + 2] + zprt[row * 4 + 3]);
        float zn  = sqrtf(zn2);
        float r   = R[k0 + row];
        float un  = fmaxf(fabsf(r) * zn, 1e-15f);
        float s   = -tanhf(un) * r / un;
        float th  = tanhf(r);
        float ic2 = 1.0f - th * th;      // 1/cosh(r)^2
        float an  = zn * ic2;
        float t   = ic2 / fmaxf(an, 1e-12f);
        s_s[row]   = s;
        s_t[row]   = t;
        s_x2[row]  = s * s * zn2;
        s_xa[row]  = s * zn2 * t;
        s_an2[row] = 2.0f * an;
    }
    __syncthreads();

    // ---- tensor GEMM: 8 warps (2m x 4n), warp tile 16m x 8n, m16n8k16 bf16 ----
    const int mw = (warp >> 2) * 16;      // 0,16
    const int nw = (warp & 3) * 8;        // 0,8,16,24
    const int g  = lane >> 2;
    const int c  = lane & 3;

    // A ldmatrix.x4: 16 rows x k16; lanes 0-15 -> rows, lanes 16-31 -> +16B (k8-15)
    const int rowA = mw + (lane & 15);
    const int offA = (lane >> 4) * 16;             // bytes
    // B ldmatrix.x4: 8 rows x k32 (4 k8-chunks); lane group i (8 lanes) -> k-chunk i
    const int rowB = nw + (lane & 7);
    const int offB = (lane >> 3) * 16;             // bytes: 0,16,32,48

    uint32_t aAH = cvta_smem(AHI) + rowA * (PB * 2) + offA;
    uint32_t aAL = cvta_smem(ALO) + rowA * (PB * 2) + offA;
    uint32_t aBH = cvta_smem(ZHI) + rowB * (PB * 2) + offB;
    uint32_t aBL = cvta_smem(ZLO) + rowB * (PB * 2) + offB;

    float accP[4] = {0,0,0,0};   // hi*hi
    float accQ[4] = {0,0,0,0};   // hi*lo
    float accS[4] = {0,0,0,0};   // lo*hi

    #pragma unroll
    for (int t = 0; t < DD / 32; t++) {          // 8 iterations of k32
        const uint32_t oA = t * 64;              // 32 bf16 = 64 bytes
        uint32_t aH0[4], aH1[4], aL0[4], aL1[4], bH[4], bL[4];
        ldmat_x4(aH0, aAH + oA);
        ldmat_x4(aH1, aAH + oA + 32);
        ldmat_x4(aL0, aAL + oA);
        ldmat_x4(aL1, aAL + oA + 32);
        ldmat_x4(bH,  aBH + oA);
        ldmat_x4(bL,  aBL + oA);

        mma_bf16(accP, aH0, bH[0], bH[1]);
        mma_bf16(accQ, aH0, bL[0], bL[1]);
        mma_bf16(accS, aL0, bH[0], bH[1]);
        mma_bf16(accP, aH1, bH[2], bH[3]);
        mma_bf16(accQ, aH1, bL[2], bL[3]);
        mma_bf16(accS, aL1, bH[2], bH[3]);
    }

    // ---- epilogue: 4 outputs per thread, float2 stores ----
    const int brow[2] = { mw + g, mw + g + 8 };
    const int kl = nw + 2 * c;
    const float s0  = s_s[kl],   s1  = s_s[kl + 1];
    const float t0  = s_t[kl],   t1  = s_t[kl + 1];
    const float x20 = s_x2[kl],  x21 = s_x2[kl + 1];
    const float xa0 = s_xa[kl],  xa1 = s_xa[kl + 1];
    const float a20 = s_an2[kl], a21 = s_an2[kl + 1];
    const float T0 = 1.0f - x20, T1 = 1.0f - x21;

    #pragma unroll
    for (int i = 0; i < 2; i++) {
        const float y2 = s_y2[brow[i]];
        const float g0 = accP[i * 2 + 0] + accQ[i * 2 + 0] + accS[i * 2 + 0];
        const float g1 = accP[i * 2 + 1] + accQ[i * 2 + 1] + accS[i * 2 + 1];

        float xy = s0 * g0;
        float ya = t0 * g0;
        float Sv  = fmaf(2.0f, xy, 1.0f) + y2;
        float den = fmaf(2.0f, xy, 1.0f) + x20 * y2;
        float Pv  = Sv * Sv * x20 + 2.0f * Sv * T0 * xy + T0 * T0 * y2;
        float v0  = 2.0f * (Sv * xa0 + T0 * ya) * den / (den * den - Pv);
        float o0  = a20 * asinhf(v0);

        xy  = s1 * g1;
        ya  = t1 * g1;
        Sv  = fmaf(2.0f, xy, 1.0f) + y2;
        den = fmaf(2.0f, xy, 1.0f) + x21 * y2;
        Pv  = Sv * Sv * x21 + 2.0f * Sv * T1 * xy + T1 * T1 * y2;
        float v1 = 2.0f * (Sv * xa1 + T1 * ya) * den / (den * den - Pv);
        float o1 = a21 * asinhf(v1);

        *reinterpret_cast<float2*>(&Out[(size_t)(b0 + brow[i]) * KK + (k0 + kl)]) =
            make_float2(o0, o1);
    }
}

extern "C" void kernel_launch(void* const* d_in, const int* in_sizes, int n_in,
                              void* d_out, int out_size)
{
    const float* Y = (const float*)d_in[0];   // output_before (2048, 256)
    const float* Z = (const float*)d_in[1];   // z_mlr (128, 256)
    const float* R = (const float*)d_in[2];   // mlr_r (128, 1)
    float* Out = (float*)d_out;               // (2048, 128)

    size_t shmem = (size_t)(2 * BM * PB + 2 * BN * PB) * sizeof(__nv_bfloat16)
                 + (size_t)(256 + 5 * BN + BM) * sizeof(float);
    cudaFuncSetAttribute(mlr_logits_kernel,
                         cudaFuncAttributeMaxDynamicSharedMemorySize, (int)shmem);

    dim3 grid(BB / BM, KK / BN);   // 64 x 4 = 256 blocks
    dim3 block(NTHREADS);
    mlr_logits_kernel<<<grid, block, shmem>>>(Y, Z, R, Out);
}